// round 14
// baseline (speedup 1.0000x reference)
#include <cuda_runtime.h>
#include <cuda_fp16.h>
#include <cstdint>
#include <cstddef>

#define BB 128
#define TT 1000
#define II 64
#define HH 512
#define ALPHA 0.2f

#define CLUSTER 4
#define H_TILE 128      // h rows per CTA
#define NTHR 256        // 8 warps, warp = one 16-row M-tile, full K
#define NWARP 8
#define KQ 36           // 576/16 k-steps (32 r + 4 x)
#define RCNT 2304       // u32 per buffer: 36*8*4*2
#define TXP 2048        // per-peer tx: 256 threads * 8 B

// rbuf u32 layout: idx(kq, n, m, j) = ((kq*8 + n)*4 + m)*2 + j
// u32(kq,n,m,j) = halves (k = 16kq + 8j + 2m, +1), column b = n.
// MMA B-frag read: lane-linear conflict-free LDS.64 per kq.
__device__ __forceinline__ int ridx(int kq, int n, int m, int j) {
    return ((kq * 8 + n) * 4 + m) * 2 + j;
}

static __device__ __forceinline__ uint32_t s2u(const void* p) {
    return (uint32_t)__cvta_generic_to_shared(p);
}
static __device__ __forceinline__ uint32_t h2_as_u32(half2 h) {
    uint32_t u; __builtin_memcpy(&u, &h, 4); return u;
}
static __device__ __forceinline__ uint32_t mapa_rank(uint32_t addr, uint32_t rank) {
    uint32_t r;
    asm volatile("mapa.shared::cluster.u32 %0, %1, %2;" : "=r"(r) : "r"(addr), "r"(rank));
    return r;
}
// remote store with transaction completion on the (pre-mapped) peer mbarrier
static __device__ __forceinline__ void st_async_u64_raw(uint32_t raddr, uint32_t rmbar,
                                                        unsigned long long v) {
    asm volatile("st.async.shared::cluster.mbarrier::complete_tx::bytes.u64 [%0], %1, [%2];"
                 :: "r"(raddr), "l"(v), "r"(rmbar) : "memory");
}
static __device__ __forceinline__ void mbar_init(uint32_t addr, uint32_t cnt) {
    asm volatile("mbarrier.init.shared.b64 [%0], %1;" :: "r"(addr), "r"(cnt) : "memory");
}
static __device__ __forceinline__ void mbar_arm_tx(uint32_t addr, uint32_t tx) {
    asm volatile("mbarrier.arrive.expect_tx.shared::cta.b64 _, [%0], %1;"
                 :: "r"(addr), "r"(tx) : "memory");
}
static __device__ __forceinline__ void mbar_wait_acq(uint32_t addr, uint32_t parity) {
    asm volatile(
        "{.reg .pred P;\nWL%=:\n\t"
        "mbarrier.try_wait.parity.acquire.cluster.shared::cta.b64 P, [%0], %1;\n\t"
        "@!P bra WL%=;\n}"
        :: "r"(addr), "r"(parity) : "memory");
}
static __device__ __forceinline__ void mma_f16(float c[4], const uint32_t a[4], uint32_t b0, uint32_t b1) {
    asm volatile(
        "mma.sync.aligned.m16n8k16.row.col.f32.f16.f16.f32 "
        "{%0,%1,%2,%3}, {%4,%5,%6,%7}, {%8,%9}, {%0,%1,%2,%3};"
        : "+f"(c[0]), "+f"(c[1]), "+f"(c[2]), "+f"(c[3])
        : "r"(a[0]), "r"(a[1]), "r"(a[2]), "r"(a[3]), "r"(b0), "r"(b1));
}
static __device__ __forceinline__ float tanh_fast(float x) {
    float y; asm("tanh.approx.f32 %0, %1;" : "=f"(y) : "f"(x)); return y;
}

// grid = 64 CTAs in 16 clusters of 4. Cluster g: b rows [g*8, g*8+8).
// CTA rank r: h rows [r*128, +128). Per step per CTA:
// drive[128h, 8b] = W_cat[128h, 576k] . rcat[8b, 576k], fp16 HMMA fp32 acc.
// W register-resident in SLOT order: slots 0..7 own-rank r block, 8..11 x,
// 12..19 / 20..27 / 28..35 = peers rank+1/+2/+3. PER-PEER tx barriers:
// mbar[parity][c-1] completes when peer rank+c's 2048 B for that step land,
// so phase-2 waits pipeline against MMA on earlier peers' data.
// Phase ledger: barrier set mb[q] serves steps with (t&1)==q; its parity
// flips once per use, tracked by ph[q], which only advances when a wait
// actually occurred (t>0) — the unconditional flip was R13's deadlock.
__global__ void __launch_bounds__(NTHR, 1) __cluster_dims__(CLUSTER, 1, 1)
rnn_kernel(const float* __restrict__ x, const float* __restrict__ W_in,
           const float* __restrict__ b_in, const float* __restrict__ W_hh,
           const float* __restrict__ b_hh, float* __restrict__ out_r)
{
    const int tid  = threadIdx.x;
    const int wid  = tid >> 5;
    const int lane = tid & 31;
    const int rank = blockIdx.x & (CLUSTER - 1);
    const int bg   = blockIdx.x >> 2;
    const int hbase = rank * H_TILE;
    const int b0g   = bg * 8;

    __shared__ __align__(16) uint32_t rbuf[2][RCNT];
    __shared__ __align__(16) float staging[NWARP][16][12];
    __shared__ __align__(8) unsigned long long mbar[2][3];   // [parity][peer c-1]

    uint32_t mb_l[2][3];
#pragma unroll
    for (int q = 0; q < 2; q++)
#pragma unroll
        for (int c = 0; c < 3; c++) mb_l[q][c] = s2u(&mbar[q][c]);

    if (tid == 0) {
#pragma unroll
        for (int q = 0; q < 2; q++)
#pragma unroll
            for (int c = 0; c < 3; c++) mbar_init(mb_l[q][c], 1);
    }

    // zero buf0 (r(0) = 0; x region overwritten below)
    for (int i = tid; i < RCNT; i += NTHR) rbuf[0][i] = 0u;

    // ---- W fragments (A operand) in SLOT order, packed fp16, once ----
    const int hA = hbase + wid * 16 + (lane >> 2);
    const int kA = 2 * (lane & 3);
    const int r1 = (rank + 1) & 3, r2 = (rank + 2) & 3, r3 = (rank + 3) & 3;
    uint32_t a[KQ][4];
#pragma unroll
    for (int s = 0; s < KQ; s++) {
        int kq_phys;
        if (s < 8)       kq_phys = rank * 8 + s;
        else if (s < 12) kq_phys = 32 + (s - 8);
        else {
            int c = (s - 12) >> 3, i = (s - 12) & 7;
            kq_phys = (((rank + 1 + c) & 3) << 3) + i;
        }
#pragma unroll
        for (int j = 0; j < 4; j++) {
            int h = hA + ((j & 1) ? 8 : 0);
            int k = kq_phys * 16 + kA + ((j & 2) ? 8 : 0);
            float2 w;
            if (k < HH) w = *(const float2*)&W_hh[h * HH + k];
            else        w = *(const float2*)&W_in[h * II + (k - HH)];
            a[s][j] = h2_as_u32(__floats2half2_rn(w.x, w.y));
        }
    }

    // ---- epilogue / writer mapping ----
    const int wn = lane >> 2;            // local b 0..7
    const int wm = lane & 3;             // fragment m 0..3
    const int ebg = b0g + wn;
    const int kq_g = rank * 8 + wid;     // global kq of owned r slice
    const int hl0 = wid * 16 + 2 * wm;
    float bias_r[4];
#pragma unroll
    for (int i = 0; i < 4; i++) {
        int hl = hl0 + ((i >> 1) ? 8 : 0) + (i & 1);
        bias_r[i] = b_hh[hbase + hl] + b_in[hbase + hl];
    }
    float r_old[4] = {0.f, 0.f, 0.f, 0.f};
    const int sidx = ridx(kq_g, wn, wm, 0);

    // ---- hoisted remote addresses: data slot + target barrier, per buf/peer ----
    // sending to dst = rank+cc targets dst's barrier index (4-cc)-1, so that
    // each CTA's barrier [q][c-1] collects data from its peer rank+c.
    uint32_t ra_r[2][3], rm_r[2][3];
#pragma unroll
    for (int bf = 0; bf < 2; bf++)
#pragma unroll
        for (int cc = 1; cc <= 3; cc++) {
            uint32_t dstr = (uint32_t)((rank + cc) & 3);
            ra_r[bf][cc - 1] = mapa_rank(s2u(&rbuf[bf][sidx]), dstr);
            rm_r[bf][cc - 1] = mapa_rank(mb_l[bf][(4 - cc) - 1], dstr);
        }

    // ---- x staging mapping: one u32 per thread ----
    const int xj  = tid & 1;
    const int xm  = (tid >> 1) & 3;
    const int xkq = 32 + ((tid >> 3) & 3);
    const int xn  = tid >> 5;
    const int xi0 = (xkq - 32) * 16 + xj * 8 + 2 * xm;
    const float* xrow = &x[(size_t)(b0g + xn) * TT * II + xi0];
    const int xidx = ridx(xkq, xn, xm, xj);

    // stage x(0)
    {
        float2 xv = *(const float2*)&xrow[0];
        rbuf[0][xidx] = h2_as_u32(__floats2half2_rn(xv.x, xv.y));
    }
    __syncthreads();
    // arm all 6 barriers BEFORE the cluster barrier: no peer store can
    // precede its expect_tx.
    if (tid == 0) {
#pragma unroll
        for (int q = 0; q < 2; q++)
#pragma unroll
            for (int c = 0; c < 3; c++) mbar_arm_tx(mb_l[q][c], TXP);
    }
    asm volatile("barrier.cluster.arrive.aligned;" ::: "memory");
    asm volatile("barrier.cluster.wait.aligned;"   ::: "memory");

    int ph[2] = {0, 0};

#pragma unroll 1
    for (int t = 0; t < TT; t++) {
        const int p = t & 1;
        int tn = (t + 1 < TT) ? t + 1 : TT - 1;
        float2 xv = *(const float2*)&xrow[(size_t)tn * II];

        const uint32_t* rbp  = &rbuf[p][lane * 2];
        const uint32_t* pown = rbp + rank * 512;
        const uint32_t* px   = rbp + 32 * 64;
        const uint32_t* pr1  = rbp + r1 * 512;
        const uint32_t* pr2  = rbp + r2 * 512;
        const uint32_t* pr3  = rbp + r3 * 512;
        const uint32_t php = (uint32_t)ph[p];

        float c[4][4];
#pragma unroll
        for (int q = 0; q < 4; q++)
#pragma unroll
            for (int r = 0; r < 4; r++) c[q][r] = 0.f;

        // ---- phase 1: local slots (own r block + x) — no wait needed ----
#pragma unroll
        for (int i = 0; i < 8; i++) {
            uint2 bv = *(const uint2*)&pown[i * 64];
            mma_f16(c[i & 3], a[i], bv.x, bv.y);
        }
#pragma unroll
        for (int i = 0; i < 4; i++) {
            uint2 bv = *(const uint2*)&px[i * 64];
            mma_f16(c[i & 3], a[8 + i], bv.x, bv.y);
        }

        // ---- peer r1: wait its barrier, then its 8 slots ----
        if (t > 0) {
            mbar_wait_acq(mb_l[p][0], php);
            if (tid == 0) mbar_arm_tx(mb_l[p][0], TXP);   // re-arm for step t+2
        }
#pragma unroll
        for (int i = 0; i < 8; i++) {
            uint2 bv = *(const uint2*)&pr1[i * 64];
            mma_f16(c[i & 3], a[12 + i], bv.x, bv.y);
        }

        // ---- peer r2 ----
        if (t > 0) {
            mbar_wait_acq(mb_l[p][1], php);
            if (tid == 0) mbar_arm_tx(mb_l[p][1], TXP);
        }
#pragma unroll
        for (int i = 0; i < 8; i++) {
            uint2 bv = *(const uint2*)&pr2[i * 64];
            mma_f16(c[(i + 1) & 3], a[20 + i], bv.x, bv.y);
        }

        // ---- peer r3 ----
        if (t > 0) {
            mbar_wait_acq(mb_l[p][2], php);
            if (tid == 0) mbar_arm_tx(mb_l[p][2], TXP);
            ph[p] ^= 1;    // phase advances ONLY when a wait occurred (fixes
                           // R13 deadlock: flipping at t=0 desynced the ledger)
        }
#pragma unroll
        for (int i = 0; i < 8; i++) {
            uint2 bv = *(const uint2*)&pr3[i * 64];
            mma_f16(c[(i + 2) & 3], a[28 + i], bv.x, bv.y);
        }

        float cf[4];
#pragma unroll
        for (int r = 0; r < 4; r++)
            cf[r] = (c[0][r] + c[1][r]) + (c[2][r] + c[3][r]);

        // ---- transpose via per-warp staging ----
        {
            int rr = lane >> 2, cc = 2 * (lane & 3);
            *(float2*)&staging[wid][rr][cc]     = make_float2(cf[0], cf[1]);
            *(float2*)&staging[wid][rr + 8][cc] = make_float2(cf[2], cf[3]);
        }
        __syncwarp();

        float rn[4];
#pragma unroll
        for (int i = 0; i < 4; i++) {
            int row = 2 * wm + ((i >> 1) ? 8 : 0) + (i & 1);
            float s = staging[wid][row][wn] + bias_r[i];
            float d = tanh_fast(s);
            rn[i] = (1.0f - ALPHA) * r_old[i] + ALPHA * d;
            r_old[i] = rn[i];
        }

        // ---- exchange: owned fragment pair -> peers (st.async) + self ----
        unsigned long long pv =
            (unsigned long long)h2_as_u32(__floats2half2_rn(rn[0], rn[1]))
            | ((unsigned long long)h2_as_u32(__floats2half2_rn(rn[2], rn[3])) << 32);
        uint32_t* dstb = rbuf[p ^ 1];
        *(unsigned long long*)&dstb[sidx] = pv;            // self, generic STS
        const int nb = p ^ 1;                              // buffer/parity of step t+1
        st_async_u64_raw(ra_r[nb][0], rm_r[nb][0], pv);
        st_async_u64_raw(ra_r[nb][1], rm_r[nb][1], pv);
        st_async_u64_raw(ra_r[nb][2], rm_r[nb][2], pv);
        // stage x(t+1) (local region of next buffer)
        dstb[xidx] = h2_as_u32(__floats2half2_rn(xv.x, xv.y));

        // out_r store — off the exchange critical path
        {
            size_t ob = ((size_t)t * BB + ebg) * HH + hbase + hl0;
            *(float2*)&out_r[ob]     = make_float2(rn[0], rn[1]);
            *(float2*)&out_r[ob + 8] = make_float2(rn[2], rn[3]);
        }

        // local visibility of self/x STS for next phase 1; keeps fast warps
        // from overwriting a buffer slow warps of this CTA still read.
        __syncthreads();
    }

    // terminal cluster sync: no CTA may exit while peers' st.async stores
    // targeting this CTA's SMEM/mbarriers can still be in flight.
    asm volatile("barrier.cluster.arrive.aligned;" ::: "memory");
    asm volatile("barrier.cluster.wait.aligned;"   ::: "memory");
}

// decision[t,b] = dot(output[t,b,:], W_out) + b_out   (1 warp per row)
__global__ void __launch_bounds__(256)
decision_kernel(const float* __restrict__ out_r, const float* __restrict__ W_out,
                const float* __restrict__ b_out, float* __restrict__ dec)
{
    int wg = blockIdx.x * 8 + (threadIdx.x >> 5);
    int lane = threadIdx.x & 31;
    if (wg >= TT * BB) return;
    const float* row = out_r + (size_t)wg * HH;
    float s = 0.0f;
#pragma unroll
    for (int c = 0; c < 4; c++) {
        int h = c * 128 + lane * 4;
        float4 v = *(const float4*)&row[h];
        float4 w = *(const float4*)&W_out[h];
        s += v.x * w.x + v.y * w.y + v.z * w.z + v.w * w.w;
    }
#pragma unroll
    for (int o = 16; o; o >>= 1) s += __shfl_down_sync(0xffffffffu, s, o);
    if (lane == 0) dec[wg] = s + b_out[0];
}

extern "C" void kernel_launch(void* const* d_in, const int* in_sizes, int n_in,
                              void* d_out, int out_size) {
    const float* x     = (const float*)d_in[0];
    const float* W_in  = (const float*)d_in[1];
    const float* b_in  = (const float*)d_in[2];
    const float* W_hh  = (const float*)d_in[3];
    const float* b_hh  = (const float*)d_in[4];
    const float* W_out = (const float*)d_in[5];
    const float* b_out = (const float*)d_in[6];

    float* dec   = (float*)d_out;                    // [T*B]
    float* out_r = (float*)d_out + (size_t)TT * BB;  // [T*B*H]

    rnn_kernel<<<BB / 2, NTHR>>>(x, W_in, b_in, W_hh, b_hh, out_r);
    decision_kernel<<<(TT * BB) / 8, 256>>>(out_r, W_out, b_out, dec);
}

// round 15
// speedup vs baseline: 1.5247x; 1.5247x over previous
#include <cuda_runtime.h>
#include <cuda_fp16.h>
#include <cstdint>
#include <cstddef>

#define BB 128
#define TT 1000
#define II 64
#define HH 512
#define ALPHA 0.2f

#define CLUSTER 4
#define H_TILE 128      // h rows per CTA
#define NTHR 256        // 8 warps, warp = one 16-row M-tile, full K
#define NWARP 8
#define KQ 36           // 576/16 k-steps (32 r + 4 x)
#define RCNT 2304       // u32 per buffer: 36*8*4*2
#define TX_BYTES 6144   // 3 peers * 256 threads * 8 B per step

// decision partials: [t][b][rank*8+wid] summed by dec_reduce (fixed order)
__device__ float g_decpart[TT * BB * 32];

// rbuf u32 layout: idx(kq, n, m, j) = ((kq*8 + n)*4 + m)*2 + j
// u32(kq,n,m,j) = halves (k = 16kq + 8j + 2m, +1), column b = n.
// MMA B-frag read: lane-linear conflict-free LDS.64 per kq.
__device__ __forceinline__ int ridx(int kq, int n, int m, int j) {
    return ((kq * 8 + n) * 4 + m) * 2 + j;
}

static __device__ __forceinline__ uint32_t s2u(const void* p) {
    return (uint32_t)__cvta_generic_to_shared(p);
}
static __device__ __forceinline__ uint32_t h2_as_u32(half2 h) {
    uint32_t u; __builtin_memcpy(&u, &h, 4); return u;
}
static __device__ __forceinline__ uint32_t mapa_rank(uint32_t addr, uint32_t rank) {
    uint32_t r;
    asm volatile("mapa.shared::cluster.u32 %0, %1, %2;" : "=r"(r) : "r"(addr), "r"(rank));
    return r;
}
// remote store with transaction completion on the (pre-mapped) peer mbarrier
static __device__ __forceinline__ void st_async_u64_raw(uint32_t raddr, uint32_t rmbar,
                                                        unsigned long long v) {
    asm volatile("st.async.shared::cluster.mbarrier::complete_tx::bytes.u64 [%0], %1, [%2];"
                 :: "r"(raddr), "l"(v), "r"(rmbar) : "memory");
}
static __device__ __forceinline__ void mbar_init(uint32_t addr, uint32_t cnt) {
    asm volatile("mbarrier.init.shared.b64 [%0], %1;" :: "r"(addr), "r"(cnt) : "memory");
}
static __device__ __forceinline__ void mbar_arm_tx(uint32_t addr, uint32_t tx) {
    asm volatile("mbarrier.arrive.expect_tx.shared::cta.b64 _, [%0], %1;"
                 :: "r"(addr), "r"(tx) : "memory");
}
static __device__ __forceinline__ void mbar_wait_acq(uint32_t addr, uint32_t parity) {
    asm volatile(
        "{.reg .pred P;\nWL%=:\n\t"
        "mbarrier.try_wait.parity.acquire.cluster.shared::cta.b64 P, [%0], %1;\n\t"
        "@!P bra WL%=;\n}"
        :: "r"(addr), "r"(parity) : "memory");
}
static __device__ __forceinline__ void mma_f16(float c[4], const uint32_t a[4], uint32_t b0, uint32_t b1) {
    asm volatile(
        "mma.sync.aligned.m16n8k16.row.col.f32.f16.f16.f32 "
        "{%0,%1,%2,%3}, {%4,%5,%6,%7}, {%8,%9}, {%0,%1,%2,%3};"
        : "+f"(c[0]), "+f"(c[1]), "+f"(c[2]), "+f"(c[3])
        : "r"(a[0]), "r"(a[1]), "r"(a[2]), "r"(a[3]), "r"(b0), "r"(b1));
}
static __device__ __forceinline__ float tanh_fast(float x) {
    float y; asm("tanh.approx.f32 %0, %1;" : "=f"(y) : "f"(x)); return y;
}

// grid = 64 CTAs in 16 clusters of 4. Cluster g: b rows [g*8, g*8+8).
// CTA rank r: h rows [r*128, +128). Per step per CTA:
// drive[128h, 8b] = W_cat[128h, 576k] . rcat[8b, 576k], fp16 HMMA fp32 acc.
// W register-resident in SLOT order: slots 0..7 own-rank r block, 8..11 x,
// 12..35 peer blocks (ring order). Phase-1 MMA (local slots) runs before the
// tx-barrier wait (monolithic per parity — R14 showed per-peer splits lose).
// Exchange: st.async per-thread fragment stores carry complete_tx to the
// peers' mbarriers; decision partials are computed in the post-send slack
// and written to g_decpart for the deterministic dec_reduce kernel.
__global__ void __launch_bounds__(NTHR, 1) __cluster_dims__(CLUSTER, 1, 1)
rnn_kernel(const float* __restrict__ x, const float* __restrict__ W_in,
           const float* __restrict__ b_in, const float* __restrict__ W_hh,
           const float* __restrict__ b_hh, const float* __restrict__ W_out,
           float* __restrict__ out_r)
{
    const int tid  = threadIdx.x;
    const int wid  = tid >> 5;
    const int lane = tid & 31;
    const int rank = blockIdx.x & (CLUSTER - 1);
    const int bg   = blockIdx.x >> 2;
    const int hbase = rank * H_TILE;
    const int b0g   = bg * 8;

    __shared__ __align__(16) uint32_t rbuf[2][RCNT];
    __shared__ __align__(16) float staging[NWARP][16][12];
    __shared__ __align__(8) unsigned long long mbar[2];

    const uint32_t mb_a[2] = { s2u(&mbar[0]), s2u(&mbar[1]) };

    if (tid == 0) {
        mbar_init(mb_a[0], 1);
        mbar_init(mb_a[1], 1);
    }

    // zero buf0 (r(0) = 0; x region overwritten below)
    for (int i = tid; i < RCNT; i += NTHR) rbuf[0][i] = 0u;

    // ---- W fragments (A operand) in SLOT order, packed fp16, once ----
    const int hA = hbase + wid * 16 + (lane >> 2);
    const int kA = 2 * (lane & 3);
    const int r1 = (rank + 1) & 3, r2 = (rank + 2) & 3, r3 = (rank + 3) & 3;
    uint32_t a[KQ][4];
#pragma unroll
    for (int s = 0; s < KQ; s++) {
        int kq_phys;
        if (s < 8)       kq_phys = rank * 8 + s;
        else if (s < 12) kq_phys = 32 + (s - 8);
        else {
            int c = (s - 12) >> 3, i = (s - 12) & 7;
            kq_phys = (((rank + 1 + c) & 3) << 3) + i;
        }
#pragma unroll
        for (int j = 0; j < 4; j++) {
            int h = hA + ((j & 1) ? 8 : 0);
            int k = kq_phys * 16 + kA + ((j & 2) ? 8 : 0);
            float2 w;
            if (k < HH) w = *(const float2*)&W_hh[h * HH + k];
            else        w = *(const float2*)&W_in[h * II + (k - HH)];
            a[s][j] = h2_as_u32(__floats2half2_rn(w.x, w.y));
        }
    }

    // ---- epilogue / writer mapping ----
    const int wn = lane >> 2;            // local b 0..7
    const int wm = lane & 3;             // fragment m 0..3
    const int ebg = b0g + wn;
    const int kq_g = rank * 8 + wid;     // global kq of owned r slice
    const int hl0 = wid * 16 + 2 * wm;   // owned h: hl0, +1, +8, +9
    float bias_r[4], wout[4];
#pragma unroll
    for (int i = 0; i < 4; i++) {
        int hl = hl0 + ((i >> 1) ? 8 : 0) + (i & 1);
        bias_r[i] = b_hh[hbase + hl] + b_in[hbase + hl];
        wout[i]   = W_out[hbase + hl];
    }
    float r_old[4] = {0.f, 0.f, 0.f, 0.f};
    const int sidx = ridx(kq_g, wn, wm, 0);
    float* decslot = &g_decpart[(size_t)ebg * 32 + rank * 8 + wid];

    // ---- hoisted remote addresses (data slot + peer barrier, per buffer) ----
    uint32_t ra_r[2][3], rm_r[2][3];
#pragma unroll
    for (int bf = 0; bf < 2; bf++)
#pragma unroll
        for (int cc = 1; cc <= 3; cc++) {
            uint32_t dstr = (uint32_t)((rank + cc) & 3);
            ra_r[bf][cc - 1] = mapa_rank(s2u(&rbuf[bf][sidx]), dstr);
            rm_r[bf][cc - 1] = mapa_rank(mb_a[bf], dstr);
        }

    // ---- x staging mapping: one u32 per thread ----
    const int xj  = tid & 1;
    const int xm  = (tid >> 1) & 3;
    const int xkq = 32 + ((tid >> 3) & 3);
    const int xn  = tid >> 5;
    const int xi0 = (xkq - 32) * 16 + xj * 8 + 2 * xm;
    const float* xrow = &x[(size_t)(b0g + xn) * TT * II + xi0];
    const int xidx = ridx(xkq, xn, xm, xj);

    // stage x(0)
    {
        float2 xv = *(const float2*)&xrow[0];
        rbuf[0][xidx] = h2_as_u32(__floats2half2_rn(xv.x, xv.y));
    }
    __syncthreads();
    // arm both barriers BEFORE the cluster barrier so no peer store can
    // precede its expect_tx.
    if (tid == 0) {
        mbar_arm_tx(mb_a[0], TX_BYTES);
        mbar_arm_tx(mb_a[1], TX_BYTES);
    }
    asm volatile("barrier.cluster.arrive.aligned;" ::: "memory");
    asm volatile("barrier.cluster.wait.aligned;"   ::: "memory");

    int ph0 = 0, ph1 = 0;

#pragma unroll 1
    for (int t = 0; t < TT; t++) {
        const int p = t & 1;
        int tn = (t + 1 < TT) ? t + 1 : TT - 1;
        float2 xv = *(const float2*)&xrow[(size_t)tn * II];

        const uint32_t* rbp  = &rbuf[p][lane * 2];
        const uint32_t* pown = rbp + rank * 512;
        const uint32_t* px   = rbp + 32 * 64;
        const uint32_t* pr1  = rbp + r1 * 512;
        const uint32_t* pr2  = rbp + r2 * 512;
        const uint32_t* pr3  = rbp + r3 * 512;

        float c[4][4];
#pragma unroll
        for (int q = 0; q < 4; q++)
#pragma unroll
            for (int r = 0; r < 4; r++) c[q][r] = 0.f;

        // ---- phase 1: local slots (own r block + x) — no wait needed ----
#pragma unroll
        for (int i = 0; i < 8; i++) {
            uint2 bv = *(const uint2*)&pown[i * 64];
            mma_f16(c[i & 3], a[i], bv.x, bv.y);
        }
#pragma unroll
        for (int i = 0; i < 4; i++) {
            uint2 bv = *(const uint2*)&px[i * 64];
            mma_f16(c[i & 3], a[8 + i], bv.x, bv.y);
        }

        // ---- wait for this step's remote data (tx barrier), then re-arm ----
        if (t > 0) {
            if (p) {
                mbar_wait_acq(mb_a[1], (uint32_t)ph1);
                if (tid == 0) mbar_arm_tx(mb_a[1], TX_BYTES);  // for step t+2
                ph1 ^= 1;
            } else {
                mbar_wait_acq(mb_a[0], (uint32_t)ph0);
                if (tid == 0) mbar_arm_tx(mb_a[0], TX_BYTES);  // for step t+2
                ph0 ^= 1;
            }
        }

        // ---- phase 2: remote slots ----
#pragma unroll
        for (int i = 0; i < 8; i++) {
            uint2 b1 = *(const uint2*)&pr1[i * 64];
            mma_f16(c[(3 * i) & 3], a[12 + i], b1.x, b1.y);
            uint2 b2 = *(const uint2*)&pr2[i * 64];
            mma_f16(c[(3 * i + 1) & 3], a[20 + i], b2.x, b2.y);
            uint2 b3 = *(const uint2*)&pr3[i * 64];
            mma_f16(c[(3 * i + 2) & 3], a[28 + i], b3.x, b3.y);
        }
        float cf[4];
#pragma unroll
        for (int r = 0; r < 4; r++)
            cf[r] = (c[0][r] + c[1][r]) + (c[2][r] + c[3][r]);

        // ---- transpose via per-warp staging ----
        {
            int rr = lane >> 2, cc = 2 * (lane & 3);
            *(float2*)&staging[wid][rr][cc]     = make_float2(cf[0], cf[1]);
            *(float2*)&staging[wid][rr + 8][cc] = make_float2(cf[2], cf[3]);
        }
        __syncwarp();

        float rn[4];
#pragma unroll
        for (int i = 0; i < 4; i++) {
            int row = 2 * wm + ((i >> 1) ? 8 : 0) + (i & 1);
            float s = staging[wid][row][wn] + bias_r[i];
            float d = tanh_fast(s);
            rn[i] = (1.0f - ALPHA) * r_old[i] + ALPHA * d;
            r_old[i] = rn[i];
        }

        // ---- exchange: owned fragment pair -> peers (st.async) + self ----
        unsigned long long pv =
            (unsigned long long)h2_as_u32(__floats2half2_rn(rn[0], rn[1]))
            | ((unsigned long long)h2_as_u32(__floats2half2_rn(rn[2], rn[3])) << 32);
        uint32_t* dstb = rbuf[p ^ 1];
        *(unsigned long long*)&dstb[sidx] = pv;            // self, generic STS
        const int nb = p ^ 1;                              // buffer/parity of step t+1
        st_async_u64_raw(ra_r[nb][0], rm_r[nb][0], pv);
        st_async_u64_raw(ra_r[nb][1], rm_r[nb][1], pv);
        st_async_u64_raw(ra_r[nb][2], rm_r[nb][2], pv);
        // stage x(t+1) (local region of next buffer)
        dstb[xidx] = h2_as_u32(__floats2half2_rn(xv.x, xv.y));

        // ---- post-send slack: out_r store + decision partial ----
        {
            size_t ob = ((size_t)t * BB + ebg) * HH + hbase + hl0;
            *(float2*)&out_r[ob]     = make_float2(rn[0], rn[1]);
            *(float2*)&out_r[ob + 8] = make_float2(rn[2], rn[3]);
        }
        {
            float pd = rn[0] * wout[0] + rn[1] * wout[1]
                     + rn[2] * wout[2] + rn[3] * wout[3];
            pd += __shfl_down_sync(0xffffffffu, pd, 2);
            pd += __shfl_down_sync(0xffffffffu, pd, 1);
            if (wm == 0) decslot[(size_t)t * BB * 32] = pd;
        }

        // local visibility of self/x STS for next phase 1; keeps fast warps
        // from overwriting a buffer slow warps of this CTA still read.
        __syncthreads();
    }

    // terminal cluster sync: no CTA may exit while peers' st.async stores
    // targeting this CTA's SMEM/mbarriers can still be in flight.
    asm volatile("barrier.cluster.arrive.aligned;" ::: "memory");
    asm volatile("barrier.cluster.wait.aligned;"   ::: "memory");
}

// dec[i] = b_out + sum of 32 partials (fixed order -> deterministic)
__global__ void __launch_bounds__(256)
dec_reduce(const float* __restrict__ b_out, float* __restrict__ dec)
{
    int i = blockIdx.x * 256 + threadIdx.x;
    if (i >= TT * BB) return;
    const float4* s = (const float4*)&g_decpart[(size_t)i * 32];
    float sum = 0.f;
#pragma unroll
    for (int j = 0; j < 8; j++) {
        float4 v = s[j];
        sum += (v.x + v.y) + (v.z + v.w);
    }
    dec[i] = sum + b_out[0];
}

extern "C" void kernel_launch(void* const* d_in, const int* in_sizes, int n_in,
                              void* d_out, int out_size) {
    const float* x     = (const float*)d_in[0];
    const float* W_in  = (const float*)d_in[1];
    const float* b_in  = (const float*)d_in[2];
    const float* W_hh  = (const float*)d_in[3];
    const float* b_hh  = (const float*)d_in[4];
    const float* W_out = (const float*)d_in[5];
    const float* b_out = (const float*)d_in[6];

    float* dec   = (float*)d_out;                    // [T*B]
    float* out_r = (float*)d_out + (size_t)TT * BB;  // [T*B*H]

    rnn_kernel<<<BB / 2, NTHR>>>(x, W_in, b_in, W_hh, b_hh, W_out, out_r);
    dec_reduce<<<(TT * BB + 255) / 256, 256>>>(b_out, dec);
}